// round 6
// baseline (speedup 1.0000x reference)
#include <cuda_runtime.h>
#include <cuda_bf16.h>
#include <stdint.h>
#include <math.h>

#define B_   64
#define A_   128
#define M_   8
#define D_   384
#define O0_  256
#define O2_  192
#define O4_  160

// smem pitches (bytes) for X buffers [b][k] bf16: K*2+16 -> conflict-free LDSM rows
#define P0 784     // K=384
#define P1 528     // K=256
#define P2 400     // K=192

#define X0H_OFF 0
#define X0L_OFF 50176
#define X1H_OFF 100352
#define X1L_OFF 134144
#define WB_OFF  167936           // 2 stage buffers x (hi 10240 + lo 10240)
#define WB_PITCH 80              // bytes per 32-col bf16 row (64 data + 16 pad)
#define SMEM_BYTES (167936 + 40960)
#define PF 68      // final f32 Y pitch (floats), layout [o][b]

#define NTHREADS 512

__device__ float g_partial[B_ * A_ * M_];

__device__ __forceinline__ float celu01(float x) {
    return x > 0.f ? x : 0.1f * expm1f(10.f * x);
}

__device__ __forceinline__ uint32_t smem_u32(const void* p) {
    uint32_t a;
    asm("{ .reg .u64 t; cvta.to.shared.u64 t, %1; cvt.u32.u64 %0, t; }" : "=r"(a) : "l"(p));
    return a;
}

// pack two floats to bf16x2 (lo half = x, hi half = y)
__device__ __forceinline__ uint32_t cvt2(float x, float y) {
    uint32_t r;
    asm("cvt.rn.bf16x2.f32 %0, %1, %2;" : "=r"(r) : "f"(y), "f"(x));
    return r;
}
__device__ __forceinline__ void split2(float x, float y, uint32_t& hi, uint32_t& lo) {
    hi = cvt2(x, y);
    float hx = __uint_as_float(hi << 16);
    float hy = __uint_as_float(hi & 0xFFFF0000u);
    lo = cvt2(x - hx, y - hy);
}

__device__ __forceinline__ void ldsm_x4(uint32_t& r0, uint32_t& r1, uint32_t& r2, uint32_t& r3,
                                        uint32_t addr) {
    asm volatile("ldmatrix.sync.aligned.m8n8.x4.shared.b16 {%0,%1,%2,%3}, [%4];"
                 : "=r"(r0), "=r"(r1), "=r"(r2), "=r"(r3) : "r"(addr));
}

__device__ __forceinline__ void mma16816(float c[4], const uint32_t a[4], const uint32_t b[2]) {
    asm volatile(
        "mma.sync.aligned.m16n8k16.row.col.f32.bf16.bf16.f32 "
        "{%0,%1,%2,%3}, {%4,%5,%6,%7}, {%8,%9}, {%0,%1,%2,%3};"
        : "+f"(c[0]), "+f"(c[1]), "+f"(c[2]), "+f"(c[3])
        : "r"(a[0]), "r"(a[1]), "r"(a[2]), "r"(a[3]), "r"(b[0]), "r"(b[1]));
}

// One layer: D[o][b] = celu(W[o][k] X[k][b] + bias).
// Stages: s = (kc2, mh). Stage loads W rows [mh*128, mh*128+rows) cols [kc2*32,+32)
// fp32 coalesced, splits to bf16 hi/lo in smem Wb[s&1]; warps consume A frags via
// ldmatrix. 16 warps: group g (n-half), wm = m-tile within half. 3-way split MMA.
template<int K, int O, int PIN, int POUT, bool FINAL>
__device__ __forceinline__ void layer(
    const float* __restrict__ Wg, const float* __restrict__ bias,
    const char* __restrict__ Xh, const char* __restrict__ Xl,
    char* __restrict__ Yh, char* __restrict__ Yl, float* __restrict__ Yf,
    char* __restrict__ Wb)
{
    const int tid   = threadIdx.x;
    const int lane  = tid & 31;
    const int warp  = tid >> 5;
    const int wm    = warp & 7;
    const int g     = warp >> 3;
    const int group = lane >> 2;
    const int tig   = lane & 3;
    constexpr int NK2   = K / 32;
    constexpr int NST   = NK2 * 2;
    constexpr int ROWS1 = O - 128;

    // B ldmatrix addresses: quad q selects {Xh k0, Xh k8, Xl k0, Xl k8}
    const int q = lane >> 3, rr = lane & 7;
    uint32_t xb = (q < 2 ? smem_u32(Xh) : smem_u32(Xl)) + (uint32_t)((q & 1) * 16);
    uint32_t aj[4];
#pragma unroll
    for (int j = 0; j < 4; j++)
        aj[j] = xb + (uint32_t)(((g * 4 + j) * 8 + rr) * PIN);

    // A ldmatrix lane offset inside a stage buffer
    const uint32_t wb0   = smem_u32(Wb);
    const uint32_t aoff  = (uint32_t)((wm * 16 + (lane & 15)) * WB_PITCH + ((lane >> 4) * 8) * 2);

    float acc[2][4][4];
#pragma unroll
    for (int im = 0; im < 2; im++)
#pragma unroll
        for (int j = 0; j < 4; j++)
#pragma unroll
            for (int e = 0; e < 4; e++) acc[im][j][e] = 0.f;

    uint32_t bh[2][4][2], bl[2][4][2];   // B frags for a kc-pair (reused across m-halves)
    float4 vA[2], vB[2];

    // prologue: LDG stage 0 (kc2=0, mh=0, rows=128)
#pragma unroll
    for (int c = 0; c < 2; c++) {
        int f = c * 2048 + tid * 4;
        vA[c] = *(const float4*)(Wg + (size_t)(f >> 5) * K + (f & 31));
    }

    for (int s = 0; s < NST; s++) {
        const int kc2 = s >> 1, mh = s & 1;

        // prefetch next stage's W into regs
        if (s + 1 < NST) {
            const int nkc2 = (s + 1) >> 1, nmh = (s + 1) & 1;
            const int nrows = nmh ? ROWS1 : 128;
#pragma unroll
            for (int c = 0; c < 2; c++) {
                int f = c * 2048 + tid * 4;
                if (f < nrows * 32)
                    vB[c] = *(const float4*)(Wg + (size_t)(nmh * 128 + (f >> 5)) * K
                                             + nkc2 * 32 + (f & 31));
            }
        }

        // convert + store this stage into Wb[s&1]
        {
            const int rows = mh ? ROWS1 : 128;
            char* wbh = Wb + (s & 1) * 20480;
            char* wbl = wbh + 10240;
#pragma unroll
            for (int c = 0; c < 2; c++) {
                int f = c * 2048 + tid * 4;
                if (f < rows * 32) {
                    int r = f >> 5, kl = f & 31;
                    uint32_t h0, l0, h1, l1;
                    split2(vA[c].x, vA[c].y, h0, l0);
                    split2(vA[c].z, vA[c].w, h1, l1);
                    *(uint2*)(wbh + r * WB_PITCH + kl * 2) = make_uint2(h0, h1);
                    *(uint2*)(wbl + r * WB_PITCH + kl * 2) = make_uint2(l0, l1);
                }
            }
        }
        __syncthreads();

        // B frags once per kc-pair (at mh==0), reused at mh==1
        if (mh == 0) {
#pragma unroll
            for (int kk = 0; kk < 2; kk++)
#pragma unroll
                for (int j = 0; j < 4; j++)
                    ldsm_x4(bh[kk][j][0], bh[kk][j][1], bl[kk][j][0], bl[kk][j][1],
                            aj[j] + (uint32_t)((kc2 * 2 + kk) * 32));
        }

        // consume: A frags from Wb[s&1], 3-way split MMAs
        const bool active = mh == 0 ? true : (wm * 16 < ROWS1);
        if (active) {
            const uint32_t ab = wb0 + (uint32_t)((s & 1) * 20480) + aoff;
#pragma unroll
            for (int kk = 0; kk < 2; kk++) {
                uint32_t ah[4], al[4];
                ldsm_x4(ah[0], ah[1], ah[2], ah[3], ab + (uint32_t)(kk * 32));
                ldsm_x4(al[0], al[1], al[2], al[3], ab + 10240u + (uint32_t)(kk * 32));
#pragma unroll
                for (int j = 0; j < 4; j++) {
                    mma16816(acc[mh][j], ah, bh[kk][j]);
                    mma16816(acc[mh][j], ah, bl[kk][j]);
                    mma16816(acc[mh][j], al, bh[kk][j]);
                }
            }
        }

#pragma unroll
        for (int c = 0; c < 2; c++) vA[c] = vB[c];
    }

    // epilogue
    constexpr int NMT = O / 16;
#pragma unroll
    for (int im = 0; im < 2; im++) {
        if (wm + im * 8 < NMT) {
            const int mt = wm + im * 8;
            const int o0 = mt * 16 + group;
            const int o1 = o0 + 8;
            const float bv0 = __ldg(bias + o0);
            const float bv1 = __ldg(bias + o1);
#pragma unroll
            for (int j = 0; j < 4; j++) {
                const int bc = (g * 4 + j) * 8 + tig * 2;
                float v00 = celu01(acc[im][j][0] + bv0);
                float v01 = celu01(acc[im][j][1] + bv0);
                float v10 = celu01(acc[im][j][2] + bv1);
                float v11 = celu01(acc[im][j][3] + bv1);
                if (!FINAL) {
                    __nv_bfloat16 h00 = __float2bfloat16(v00);
                    __nv_bfloat16 h01 = __float2bfloat16(v01);
                    __nv_bfloat16 h10 = __float2bfloat16(v10);
                    __nv_bfloat16 h11 = __float2bfloat16(v11);
                    *(__nv_bfloat16*)(Yh + (size_t)bc * POUT + o0 * 2)       = h00;
                    *(__nv_bfloat16*)(Yh + (size_t)(bc + 1) * POUT + o0 * 2) = h01;
                    *(__nv_bfloat16*)(Yh + (size_t)bc * POUT + o1 * 2)       = h10;
                    *(__nv_bfloat16*)(Yh + (size_t)(bc + 1) * POUT + o1 * 2) = h11;
                    *(__nv_bfloat16*)(Yl + (size_t)bc * POUT + o0 * 2)       = __float2bfloat16(v00 - __bfloat162float(h00));
                    *(__nv_bfloat16*)(Yl + (size_t)(bc + 1) * POUT + o0 * 2) = __float2bfloat16(v01 - __bfloat162float(h01));
                    *(__nv_bfloat16*)(Yl + (size_t)bc * POUT + o1 * 2)       = __float2bfloat16(v10 - __bfloat162float(h10));
                    *(__nv_bfloat16*)(Yl + (size_t)(bc + 1) * POUT + o1 * 2) = __float2bfloat16(v11 - __bfloat162float(h11));
                } else {
                    Yf[o0 * PF + bc]     = v00;
                    Yf[o0 * PF + bc + 1] = v01;
                    Yf[o1 * PF + bc]     = v10;
                    Yf[o1 * PF + bc + 1] = v11;
                }
            }
        }
    }
}

__global__ void __launch_bounds__(NTHREADS, 1)
nn_hmma(const float* __restrict__ aev,
        const float* __restrict__ w0, const float* __restrict__ b0,
        const float* __restrict__ w2, const float* __restrict__ b2,
        const float* __restrict__ w4, const float* __restrict__ b4,
        const float* __restrict__ w6, const float* __restrict__ b6)
{
    extern __shared__ char sm[];
    const int tid = threadIdx.x;
    const int am = blockIdx.x, a = am >> 3;

    // init X0 from aev: [b][k] bf16 hi/lo
#pragma unroll
    for (int it = 0; it < 24; it++) {
        int f = (it * NTHREADS + tid) * 2;
        int b = f / D_;
        int k = f % D_;
        float2 v = *(const float2*)(aev + ((size_t)b * A_ + a) * D_ + k);
        uint32_t hi, lo;
        split2(v.x, v.y, hi, lo);
        *(uint32_t*)(sm + X0H_OFF + (size_t)b * P0 + k * 2) = hi;
        *(uint32_t*)(sm + X0L_OFF + (size_t)b * P0 + k * 2) = lo;
    }
    __syncthreads();

    layer<D_, O0_, P0, P1, false>(
        w0 + (size_t)am * O0_ * D_, b0 + (size_t)am * O0_,
        sm + X0H_OFF, sm + X0L_OFF, sm + X1H_OFF, sm + X1L_OFF, nullptr, sm + WB_OFF);
    __syncthreads();

    layer<O0_, O2_, P1, P2, false>(
        w2 + (size_t)am * O2_ * O0_, b2 + (size_t)am * O2_,
        sm + X1H_OFF, sm + X1L_OFF, sm + X0H_OFF, sm + X0L_OFF, nullptr, sm + WB_OFF);
    __syncthreads();

    layer<O2_, O4_, P2, 0, true>(
        w4 + (size_t)am * O4_ * O2_, b4 + (size_t)am * O4_,
        sm + X0H_OFF, sm + X0L_OFF, nullptr, nullptr, (float*)(sm + X1H_OFF), sm + WB_OFF);
    __syncthreads();

    // final dot: energy contribution per (b, am). 512 threads: 8 per b.
    const float* Yf = (const float*)(sm + X1H_OFF);
    const float* w6p = w6 + (size_t)am * O4_;
    const int b = tid >> 3;
    const int part = tid & 7;
    float acc = 0.f;
#pragma unroll
    for (int i = 0; i < 20; i++) {
        int k = part * 20 + i;
        acc += __ldg(w6p + k) * Yf[k * PF + b];
    }
    acc += __shfl_xor_sync(0xffffffffu, acc, 1);
    acc += __shfl_xor_sync(0xffffffffu, acc, 2);
    acc += __shfl_xor_sync(0xffffffffu, acc, 4);
    if (part == 0)
        g_partial[(size_t)b * (A_ * M_) + am] = acc + __ldg(b6 + am);
}

// ---------------- output assembly ----------------
__global__ void reduce_kernel(float* __restrict__ out, int species_first) {
    __shared__ float sh[256];
    const int b = blockIdx.x;
    float s = 0.f;
    for (int i = threadIdx.x; i < A_ * M_; i += 256)
        s += g_partial[(size_t)b * (A_ * M_) + i];
    sh[threadIdx.x] = s;
    __syncthreads();
    for (int st = 128; st > 0; st >>= 1) {
        if (threadIdx.x < st) sh[threadIdx.x] += sh[threadIdx.x + st];
        __syncthreads();
    }
    if (threadIdx.x == 0)
        out[(species_first ? B_ * A_ : 0) + b] = sh[0] / (float)M_;
}

__global__ void species_kernel(const int* __restrict__ sp, float* __restrict__ out) {
    int i = blockIdx.x * 256 + threadIdx.x;
    if (i < B_ * A_) out[i] = (float)sp[i];
}

extern "C" void kernel_launch(void* const* d_in, const int* in_sizes, int n_in,
                              void* d_out, int out_size) {
    const int*   species = (const int*)  d_in[0];
    const float* aev     = (const float*)d_in[1];
    const float* w0      = (const float*)d_in[2];
    const float* b0      = (const float*)d_in[3];
    const float* w2      = (const float*)d_in[4];
    const float* b2      = (const float*)d_in[5];
    const float* w4      = (const float*)d_in[6];
    const float* b4      = (const float*)d_in[7];
    const float* w6      = (const float*)d_in[8];
    const float* b6      = (const float*)d_in[9];
    float* out = (float*)d_out;

    cudaFuncSetAttribute(nn_hmma, cudaFuncAttributeMaxDynamicSharedMemorySize, SMEM_BYTES);

    nn_hmma<<<A_ * M_, NTHREADS, SMEM_BYTES>>>(aev, w0, b0, w2, b2, w4, b4, w6, b6);

    const int species_first = (out_size >= B_ * A_ + B_) ? 1 : 0;
    if (species_first)
        species_kernel<<<(B_ * A_) / 256, 256>>>(species, out);
    reduce_kernel<<<B_, 256>>>(out, species_first);
}

// round 7
// speedup vs baseline: 1.6458x; 1.6458x over previous
#include <cuda_runtime.h>
#include <cuda_bf16.h>
#include <stdint.h>
#include <math.h>

#define B_   64
#define A_   128
#define M_   8
#define D_   384
#define O0_  256
#define O2_  192
#define O4_  160

// smem pitches (bytes) for X buffers [b][k] bf16: K*2+16 -> conflict-free LDSM rows
#define P0 784     // K=384
#define P1 528     // K=256
#define P2 400     // K=192

#define X0H_OFF 0
#define X0L_OFF 50176
#define X1H_OFF 100352
#define X1L_OFF 134144
#define SMEM_BYTES 167936
#define PF 68      // final f32 Y pitch (floats), layout [o][b]

#define NTHREADS 512

__device__ float g_partial[B_ * A_ * M_];

__device__ __forceinline__ float celu01(float x) {
    return x > 0.f ? x : 0.1f * expm1f(10.f * x);
}

__device__ __forceinline__ uint32_t smem_u32(const void* p) {
    uint32_t a;
    asm("{ .reg .u64 t; cvta.to.shared.u64 t, %1; cvt.u32.u64 %0, t; }" : "=r"(a) : "l"(p));
    return a;
}

// byte offset of logical element k within a permuted X row.
// Within each 16-col group, pair p (k=2p,2p+1) sits at phys pair (p>>1)+(p&1)*4.
// This makes B-frag lane t carry logical k (4t,4t+1) [b0] and (4t+2,4t+3) [b1],
// matching a contiguous float4 W load at col tig*4.
__device__ __forceinline__ uint32_t permb(int k) {
    int p  = (k >> 1) & 7;
    int pp = (p >> 1) + ((p & 1) << 2);
    return (uint32_t)(((k & ~15) << 1) + (pp << 2) + ((k & 1) << 1));
}

// pack two floats to bf16x2 (lo half = x, hi half = y)
__device__ __forceinline__ uint32_t cvt2(float x, float y) {
    uint32_t r;
    asm("cvt.rn.bf16x2.f32 %0, %1, %2;" : "=r"(r) : "f"(y), "f"(x));
    return r;
}
__device__ __forceinline__ void split2(float x, float y, uint32_t& hi, uint32_t& lo) {
    hi = cvt2(x, y);
    float hx = __uint_as_float(hi << 16);
    float hy = __uint_as_float(hi & 0xFFFF0000u);
    lo = cvt2(x - hx, y - hy);
}

__device__ __forceinline__ void ldsm_x4(uint32_t& r0, uint32_t& r1, uint32_t& r2, uint32_t& r3,
                                        uint32_t addr) {
    asm volatile("ldmatrix.sync.aligned.m8n8.x4.shared.b16 {%0,%1,%2,%3}, [%4];"
                 : "=r"(r0), "=r"(r1), "=r"(r2), "=r"(r3) : "r"(addr));
}

__device__ __forceinline__ void mma16816(float c[4], const uint32_t a[4], const uint32_t b[2]) {
    asm volatile(
        "mma.sync.aligned.m16n8k16.row.col.f32.bf16.bf16.f32 "
        "{%0,%1,%2,%3}, {%4,%5,%6,%7}, {%8,%9}, {%0,%1,%2,%3};"
        : "+f"(c[0]), "+f"(c[1]), "+f"(c[2]), "+f"(c[3])
        : "r"(a[0]), "r"(a[1]), "r"(a[2]), "r"(a[3]), "r"(b[0]), "r"(b[1]));
}

// One layer: D[o][b] = celu(W[o][k] X[k][b] + bias).
// 16 warps: warp = (g<<3)|wm. Group g handles n-tiles [g*4, g*4+4);
// warp wm handles m-tiles {wm, wm+8} (where < O/16). W via contiguous LDG.128
// (k-permuted B side), B frags via ldmatrix.x4. 3-way bf16 split MMA.
template<int K, int O, int PIN, int POUT, bool FINAL>
__device__ __forceinline__ void layer(
    const float* __restrict__ Wg, const float* __restrict__ bias,
    const char* __restrict__ Xh, const char* __restrict__ Xl,
    char* __restrict__ Yh, char* __restrict__ Yl, float* __restrict__ Yf)
{
    const int lane  = threadIdx.x & 31;
    const int warp  = threadIdx.x >> 5;
    const int wm    = warp & 7;
    const int g     = warp >> 3;
    const int group = lane >> 2;
    const int tig   = lane & 3;
    constexpr int NMT = O / 16;
    constexpr int NK  = K / 16;
    const int nmt = (wm + 8 < NMT) ? 2 : 1;

    // per-lane ldmatrix addresses: quad q=lane>>3 selects {Xh k0, Xh k8, Xl k0, Xl k8}
    const int q = lane >> 3;
    const int rr = lane & 7;
    uint32_t xb = (q < 2 ? smem_u32(Xh) : smem_u32(Xl)) + (uint32_t)((q & 1) * 16);
    uint32_t aj[4];
#pragma unroll
    for (int j = 0; j < 4; j++)
        aj[j] = xb + (uint32_t)(((g * 4 + j) * 8 + rr) * PIN);

    float acc[2][4][4];
#pragma unroll
    for (int im = 0; im < 2; im++)
#pragma unroll
        for (int j = 0; j < 4; j++)
#pragma unroll
            for (int e = 0; e < 4; e++) acc[im][j][e] = 0.f;

    float4 r0[2], r1[2], n0[2], n1[2];

    // prologue A loads (kc=0): two contiguous LDG.128 per im (rows group, group+8)
#pragma unroll
    for (int im = 0; im < 2; im++) {
        if (im < nmt) {
            const float* p = Wg + (size_t)(wm + im * 8) * 16 * K + group * K + tig * 4;
            r0[im] = *(const float4*)(p);
            r1[im] = *(const float4*)(p + 8 * K);
        }
    }

    for (int kc = 0; kc < NK; kc++) {
        // B fragments: one ldmatrix.x4 per n-tile (bh0, bh1, bl0, bl1)
        uint32_t bh[4][2], bl[4][2];
#pragma unroll
        for (int j = 0; j < 4; j++)
            ldsm_x4(bh[j][0], bh[j][1], bl[j][0], bl[j][1], aj[j] + (uint32_t)(kc * 32));

        // prefetch next A chunk
        if (kc + 1 < NK) {
#pragma unroll
            for (int im = 0; im < 2; im++) {
                if (im < nmt) {
                    const float* p = Wg + (size_t)(wm + im * 8) * 16 * K + group * K
                                     + (kc + 1) * 16 + tig * 4;
                    n0[im] = *(const float4*)(p);
                    n1[im] = *(const float4*)(p + 8 * K);
                }
            }
        }

#pragma unroll
        for (int im = 0; im < 2; im++) {
            if (im < nmt) {
                // slots: a0=(row g, k-lo)=r0.xy, a1=(row g+8, k-lo)=r1.xy,
                //        a2=(row g, k-hi)=r0.zw, a3=(row g+8, k-hi)=r1.zw
                uint32_t ah[4], al[4];
                split2(r0[im].x, r0[im].y, ah[0], al[0]);
                split2(r1[im].x, r1[im].y, ah[1], al[1]);
                split2(r0[im].z, r0[im].w, ah[2], al[2]);
                split2(r1[im].z, r1[im].w, ah[3], al[3]);
#pragma unroll
                for (int j = 0; j < 4; j++) {
                    mma16816(acc[im][j], ah, bh[j]);
                    mma16816(acc[im][j], ah, bl[j]);
                    mma16816(acc[im][j], al, bh[j]);
                }
            }
        }
#pragma unroll
        for (int im = 0; im < 2; im++) { r0[im] = n0[im]; r1[im] = n1[im]; }
    }

    // epilogue
#pragma unroll
    for (int im = 0; im < 2; im++) {
        if (im < nmt) {
            const int mt = wm + im * 8;
            const int o0 = mt * 16 + group;
            const int o1 = o0 + 8;
            const float bv0 = __ldg(bias + o0);
            const float bv1 = __ldg(bias + o1);
            const uint32_t po0 = permb(o0);
            const uint32_t po1 = permb(o1);
#pragma unroll
            for (int j = 0; j < 4; j++) {
                const int bc = (g * 4 + j) * 8 + tig * 2;
                float v00 = celu01(acc[im][j][0] + bv0);
                float v01 = celu01(acc[im][j][1] + bv0);
                float v10 = celu01(acc[im][j][2] + bv1);
                float v11 = celu01(acc[im][j][3] + bv1);
                if (!FINAL) {
                    __nv_bfloat16 h00 = __float2bfloat16(v00);
                    __nv_bfloat16 h01 = __float2bfloat16(v01);
                    __nv_bfloat16 h10 = __float2bfloat16(v10);
                    __nv_bfloat16 h11 = __float2bfloat16(v11);
                    *(__nv_bfloat16*)(Yh + (size_t)bc * POUT + po0)       = h00;
                    *(__nv_bfloat16*)(Yh + (size_t)(bc + 1) * POUT + po0) = h01;
                    *(__nv_bfloat16*)(Yh + (size_t)bc * POUT + po1)       = h10;
                    *(__nv_bfloat16*)(Yh + (size_t)(bc + 1) * POUT + po1) = h11;
                    *(__nv_bfloat16*)(Yl + (size_t)bc * POUT + po0)       = __float2bfloat16(v00 - __bfloat162float(h00));
                    *(__nv_bfloat16*)(Yl + (size_t)(bc + 1) * POUT + po0) = __float2bfloat16(v01 - __bfloat162float(h01));
                    *(__nv_bfloat16*)(Yl + (size_t)bc * POUT + po1)       = __float2bfloat16(v10 - __bfloat162float(h10));
                    *(__nv_bfloat16*)(Yl + (size_t)(bc + 1) * POUT + po1) = __float2bfloat16(v11 - __bfloat162float(h11));
                } else {
                    Yf[o0 * PF + bc]     = v00;
                    Yf[o0 * PF + bc + 1] = v01;
                    Yf[o1 * PF + bc]     = v10;
                    Yf[o1 * PF + bc + 1] = v11;
                }
            }
        }
    }
}

__global__ void __launch_bounds__(NTHREADS, 1)
nn_hmma(const float* __restrict__ aev,
        const float* __restrict__ w0, const float* __restrict__ b0,
        const float* __restrict__ w2, const float* __restrict__ b2,
        const float* __restrict__ w4, const float* __restrict__ b4,
        const float* __restrict__ w6, const float* __restrict__ b6)
{
    extern __shared__ char sm[];
    const int tid = threadIdx.x;
    const int am = blockIdx.x, a = am >> 3;

    // init X0 from aev: [b][k] bf16 hi/lo, k-permuted within 16-groups
#pragma unroll
    for (int it = 0; it < 24; it++) {
        int f = (it * NTHREADS + tid) * 2;
        int b = f / D_;
        int k = f % D_;
        float2 v = *(const float2*)(aev + ((size_t)b * A_ + a) * D_ + k);
        uint32_t hi, lo;
        split2(v.x, v.y, hi, lo);
        uint32_t off = permb(k);   // k even: pair-aligned
        *(uint32_t*)(sm + X0H_OFF + (size_t)b * P0 + off) = hi;
        *(uint32_t*)(sm + X0L_OFF + (size_t)b * P0 + off) = lo;
    }
    __syncthreads();

    layer<D_, O0_, P0, P1, false>(
        w0 + (size_t)am * O0_ * D_, b0 + (size_t)am * O0_,
        sm + X0H_OFF, sm + X0L_OFF, sm + X1H_OFF, sm + X1L_OFF, nullptr);
    __syncthreads();

    layer<O0_, O2_, P1, P2, false>(
        w2 + (size_t)am * O2_ * O0_, b2 + (size_t)am * O2_,
        sm + X1H_OFF, sm + X1L_OFF, sm + X0H_OFF, sm + X0L_OFF, nullptr);
    __syncthreads();

    layer<O2_, O4_, P2, 0, true>(
        w4 + (size_t)am * O4_ * O2_, b4 + (size_t)am * O4_,
        sm + X0H_OFF, sm + X0L_OFF, nullptr, nullptr, (float*)(sm + X1H_OFF));
    __syncthreads();

    // final dot: energy contribution per (b, am). 512 threads: 8 per b.
    const float* Yf = (const float*)(sm + X1H_OFF);
    const float* w6p = w6 + (size_t)am * O4_;
    const int b = tid >> 3;
    const int part = tid & 7;
    float acc = 0.f;
#pragma unroll
    for (int i = 0; i < 20; i++) {
        int k = part * 20 + i;
        acc += __ldg(w6p + k) * Yf[k * PF + b];
    }
    acc += __shfl_xor_sync(0xffffffffu, acc, 1);
    acc += __shfl_xor_sync(0xffffffffu, acc, 2);
    acc += __shfl_xor_sync(0xffffffffu, acc, 4);
    if (part == 0)
        g_partial[(size_t)b * (A_ * M_) + am] = acc + __ldg(b6 + am);
}

// ---------------- output assembly ----------------
__global__ void reduce_kernel(float* __restrict__ out, int species_first) {
    __shared__ float sh[256];
    const int b = blockIdx.x;
    float s = 0.f;
    for (int i = threadIdx.x; i < A_ * M_; i += 256)
        s += g_partial[(size_t)b * (A_ * M_) + i];
    sh[threadIdx.x] = s;
    __syncthreads();
    for (int st = 128; st > 0; st >>= 1) {
        if (threadIdx.x < st) sh[threadIdx.x] += sh[threadIdx.x + st];
        __syncthreads();
    }
    if (threadIdx.x == 0)
        out[(species_first ? B_ * A_ : 0) + b] = sh[0] / (float)M_;
}

__global__ void species_kernel(const int* __restrict__ sp, float* __restrict__ out) {
    int i = blockIdx.x * 256 + threadIdx.x;
    if (i < B_ * A_) out[i] = (float)sp[i];
}

extern "C" void kernel_launch(void* const* d_in, const int* in_sizes, int n_in,
                              void* d_out, int out_size) {
    const int*   species = (const int*)  d_in[0];
    const float* aev     = (const float*)d_in[1];
    const float* w0      = (const float*)d_in[2];
    const float* b0      = (const float*)d_in[3];
    const float* w2      = (const float*)d_in[4];
    const float* b2      = (const float*)d_in[5];
    const float* w4      = (const float*)d_in[6];
    const float* b4      = (const float*)d_in[7];
    const float* w6      = (const float*)d_in[8];
    const float* b6      = (const float*)d_in[9];
    float* out = (float*)d_out;

    cudaFuncSetAttribute(nn_hmma, cudaFuncAttributeMaxDynamicSharedMemorySize, SMEM_BYTES);

    nn_hmma<<<A_ * M_, NTHREADS, SMEM_BYTES>>>(aev, w0, b0, w2, b2, w4, b4, w6, b6);

    const int species_first = (out_size >= B_ * A_ + B_) ? 1 : 0;
    if (species_first)
        species_kernel<<<(B_ * A_) / 256, 256>>>(species, out);
    reduce_kernel<<<B_, 256>>>(out, species_first);
}

// round 8
// speedup vs baseline: 1.8635x; 1.1323x over previous
#include <cuda_runtime.h>
#include <cuda_bf16.h>
#include <stdint.h>
#include <math.h>

#define B_   64
#define A_   128
#define M_   8
#define D_   384
#define O0_  256
#define O2_  192
#define O4_  160

// smem pitches (bytes) for X buffers [b][k] bf16: K*2+16 -> conflict-free LDSM rows
#define P0 784     // K=384
#define P1 528     // K=256
#define P2 400     // K=192

#define X0H_OFF 0
#define X0L_OFF 50176
#define X1H_OFF 100352
#define X1L_OFF 134144
#define SMEM_BYTES 167936
#define PF 68      // final f32 Y pitch (floats), layout [o][b]

#define NTHREADS 512

__device__ float g_partial[B_ * A_ * M_];

__device__ __forceinline__ float celu01(float x) {
    return x > 0.f ? x : 0.1f * expm1f(10.f * x);
}

__device__ __forceinline__ uint32_t smem_u32(const void* p) {
    uint32_t a;
    asm("{ .reg .u64 t; cvta.to.shared.u64 t, %1; cvt.u32.u64 %0, t; }" : "=r"(a) : "l"(p));
    return a;
}

// byte offset of logical element k within a permuted X row (see R7):
// makes B-frag lane t carry logical k (4t,4t+1)/(4t+2,4t+3) so W loads are
// contiguous float4 at col tig*4.
__device__ __forceinline__ uint32_t permb(int k) {
    int p  = (k >> 1) & 7;
    int pp = (p >> 1) + ((p & 1) << 2);
    return (uint32_t)(((k & ~15) << 1) + (pp << 2) + ((k & 1) << 1));
}

// pack two floats to bf16x2 (lo half = x, hi half = y)
__device__ __forceinline__ uint32_t cvt2(float x, float y) {
    uint32_t r;
    asm("cvt.rn.bf16x2.f32 %0, %1, %2;" : "=r"(r) : "f"(y), "f"(x));
    return r;
}
__device__ __forceinline__ void split2(float x, float y, uint32_t& hi, uint32_t& lo) {
    hi = cvt2(x, y);
    float hx = __uint_as_float(hi << 16);
    float hy = __uint_as_float(hi & 0xFFFF0000u);
    lo = cvt2(x - hx, y - hy);
}

__device__ __forceinline__ void ldsm_x4(uint32_t& r0, uint32_t& r1, uint32_t& r2, uint32_t& r3,
                                        uint32_t addr) {
    asm volatile("ldmatrix.sync.aligned.m8n8.x4.shared.b16 {%0,%1,%2,%3}, [%4];"
                 : "=r"(r0), "=r"(r1), "=r"(r2), "=r"(r3) : "r"(addr));
}

__device__ __forceinline__ void mma16816(float c[4], const uint32_t a[4], const uint32_t b[2]) {
    asm volatile(
        "mma.sync.aligned.m16n8k16.row.col.f32.bf16.bf16.f32 "
        "{%0,%1,%2,%3}, {%4,%5,%6,%7}, {%8,%9}, {%0,%1,%2,%3};"
        : "+f"(c[0]), "+f"(c[1]), "+f"(c[2]), "+f"(c[3])
        : "r"(a[0]), "r"(a[1]), "r"(a[2]), "r"(a[3]), "r"(b[0]), "r"(b[1]));
}

// One layer: D[o][b] = celu(W[o][k] X[k][b] + bias).
// 16 warps, warp w owns m-tile w (w < O/16); each warp computes ALL 8 n-tiles.
// W loaded once per CTA (no group duplication), distance-2 prefetch.
// B frags via ldmatrix.x4 from permuted X. 3-way bf16 split MMA.
template<int K, int O, int PIN, int POUT, bool FINAL>
__device__ __forceinline__ void layer(
    const float* __restrict__ Wg, const float* __restrict__ bias,
    const char* __restrict__ Xh, const char* __restrict__ Xl,
    char* __restrict__ Yh, char* __restrict__ Yl, float* __restrict__ Yf)
{
    const int lane  = threadIdx.x & 31;
    const int warp  = threadIdx.x >> 5;
    const int group = lane >> 2;
    const int tig   = lane & 3;
    constexpr int NMT = O / 16;
    constexpr int NK  = K / 16;
    const bool active = warp < NMT;
    if (!active) return;

    // per-lane ldmatrix addresses: quad q=lane>>3 selects {Xh k0, Xh k8, Xl k0, Xl k8}
    const int q = lane >> 3;
    const int rr = lane & 7;
    uint32_t xb = (q < 2 ? smem_u32(Xh) : smem_u32(Xl)) + (uint32_t)((q & 1) * 16);
    uint32_t aj[8];
#pragma unroll
    for (int j = 0; j < 8; j++)
        aj[j] = xb + (uint32_t)((j * 8 + rr) * PIN);

    float acc[8][4];
#pragma unroll
    for (int j = 0; j < 8; j++)
#pragma unroll
        for (int e = 0; e < 4; e++) acc[j][e] = 0.f;

    const float* wp0 = Wg + (size_t)(warp * 16 + group) * K + tig * 4;
    const float* wp1 = wp0 + 8 * K;

    // parity double-buffers, prefetch distance 2
    float4 e0, e1, o0v, o1v;
    e0  = *(const float4*)(wp0);
    e1  = *(const float4*)(wp1);
    o0v = *(const float4*)(wp0 + 16);
    o1v = *(const float4*)(wp1 + 16);

#pragma unroll 2
    for (int kc = 0; kc < NK; kc++) {
        const bool even = (kc & 1) == 0;
        float4 r0 = even ? e0 : o0v;
        float4 r1 = even ? e1 : o1v;

        // B fragments: 8 n-tiles, one ldmatrix.x4 each
        uint32_t bh[8][2], bl[8][2];
#pragma unroll
        for (int j = 0; j < 8; j++)
            ldsm_x4(bh[j][0], bh[j][1], bl[j][0], bl[j][1], aj[j] + (uint32_t)(kc * 32));

        // split W chunk to bf16 hi/lo fragments
        uint32_t ah[4], al[4];
        split2(r0.x, r0.y, ah[0], al[0]);
        split2(r1.x, r1.y, ah[1], al[1]);
        split2(r0.z, r0.w, ah[2], al[2]);
        split2(r1.z, r1.w, ah[3], al[3]);

        // prefetch kc+2 into the parity buffer just consumed
        if (kc + 2 < NK) {
            const float* p0 = wp0 + (kc + 2) * 16;
            const float* p1 = wp1 + (kc + 2) * 16;
            if (even) { e0 = *(const float4*)p0;  e1 = *(const float4*)p1; }
            else      { o0v = *(const float4*)p0; o1v = *(const float4*)p1; }
        }

#pragma unroll
        for (int j = 0; j < 8; j++) {
            mma16816(acc[j], ah, bh[j]);
            mma16816(acc[j], ah, bl[j]);
            mma16816(acc[j], al, bh[j]);
        }
    }

    // epilogue
    const int o0 = warp * 16 + group;
    const int o1 = o0 + 8;
    const float bv0 = __ldg(bias + o0);
    const float bv1 = __ldg(bias + o1);
    const uint32_t po0 = permb(o0);
    const uint32_t po1 = permb(o1);
#pragma unroll
    for (int j = 0; j < 8; j++) {
        const int bc = j * 8 + tig * 2;
        float v00 = celu01(acc[j][0] + bv0);
        float v01 = celu01(acc[j][1] + bv0);
        float v10 = celu01(acc[j][2] + bv1);
        float v11 = celu01(acc[j][3] + bv1);
        if (!FINAL) {
            __nv_bfloat16 h00 = __float2bfloat16(v00);
            __nv_bfloat16 h01 = __float2bfloat16(v01);
            __nv_bfloat16 h10 = __float2bfloat16(v10);
            __nv_bfloat16 h11 = __float2bfloat16(v11);
            *(__nv_bfloat16*)(Yh + (size_t)bc * POUT + po0)       = h00;
            *(__nv_bfloat16*)(Yh + (size_t)(bc + 1) * POUT + po0) = h01;
            *(__nv_bfloat16*)(Yh + (size_t)bc * POUT + po1)       = h10;
            *(__nv_bfloat16*)(Yh + (size_t)(bc + 1) * POUT + po1) = h11;
            *(__nv_bfloat16*)(Yl + (size_t)bc * POUT + po0)       = __float2bfloat16(v00 - __bfloat162float(h00));
            *(__nv_bfloat16*)(Yl + (size_t)(bc + 1) * POUT + po0) = __float2bfloat16(v01 - __bfloat162float(h01));
            *(__nv_bfloat16*)(Yl + (size_t)bc * POUT + po1)       = __float2bfloat16(v10 - __bfloat162float(h10));
            *(__nv_bfloat16*)(Yl + (size_t)(bc + 1) * POUT + po1) = __float2bfloat16(v11 - __bfloat162float(h11));
        } else {
            Yf[o0 * PF + bc]     = v00;
            Yf[o0 * PF + bc + 1] = v01;
            Yf[o1 * PF + bc]     = v10;
            Yf[o1 * PF + bc + 1] = v11;
        }
    }
}

__global__ void __launch_bounds__(NTHREADS, 1)
nn_hmma(const float* __restrict__ aev,
        const float* __restrict__ w0, const float* __restrict__ b0,
        const float* __restrict__ w2, const float* __restrict__ b2,
        const float* __restrict__ w4, const float* __restrict__ b4,
        const float* __restrict__ w6, const float* __restrict__ b6)
{
    extern __shared__ char sm[];
    const int tid = threadIdx.x;
    const int am = blockIdx.x, a = am >> 3;

    // init X0 from aev: [b][k] bf16 hi/lo, k-permuted within 16-groups
#pragma unroll
    for (int it = 0; it < 24; it++) {
        int f = (it * NTHREADS + tid) * 2;
        int b = f / D_;
        int k = f % D_;
        float2 v = *(const float2*)(aev + ((size_t)b * A_ + a) * D_ + k);
        uint32_t hi, lo;
        split2(v.x, v.y, hi, lo);
        uint32_t off = permb(k);   // k even: pair-aligned
        *(uint32_t*)(sm + X0H_OFF + (size_t)b * P0 + off) = hi;
        *(uint32_t*)(sm + X0L_OFF + (size_t)b * P0 + off) = lo;
    }
    __syncthreads();

    layer<D_, O0_, P0, P1, false>(
        w0 + (size_t)am * O0_ * D_, b0 + (size_t)am * O0_,
        sm + X0H_OFF, sm + X0L_OFF, sm + X1H_OFF, sm + X1L_OFF, nullptr);
    __syncthreads();

    layer<O0_, O2_, P1, P2, false>(
        w2 + (size_t)am * O2_ * O0_, b2 + (size_t)am * O2_,
        sm + X1H_OFF, sm + X1L_OFF, sm + X0H_OFF, sm + X0L_OFF, nullptr);
    __syncthreads();

    layer<O2_, O4_, P2, 0, true>(
        w4 + (size_t)am * O4_ * O2_, b4 + (size_t)am * O4_,
        sm + X0H_OFF, sm + X0L_OFF, nullptr, nullptr, (float*)(sm + X1H_OFF));
    __syncthreads();

    // final dot: energy contribution per (b, am). 512 threads: 8 per b.
    const float* Yf = (const float*)(sm + X1H_OFF);
    const float* w6p = w6 + (size_t)am * O4_;
    const int b = tid >> 3;
    const int part = tid & 7;
    float acc = 0.f;
#pragma unroll
    for (int i = 0; i < 20; i++) {
        int k = part * 20 + i;
        acc += __ldg(w6p + k) * Yf[k * PF + b];
    }
    acc += __shfl_xor_sync(0xffffffffu, acc, 1);
    acc += __shfl_xor_sync(0xffffffffu, acc, 2);
    acc += __shfl_xor_sync(0xffffffffu, acc, 4);
    if (part == 0)
        g_partial[(size_t)b * (A_ * M_) + am] = acc + __ldg(b6 + am);
}

// ---------------- output assembly ----------------
__global__ void reduce_kernel(float* __restrict__ out, int species_first) {
    __shared__ float sh[256];
    const int b = blockIdx.x;
    float s = 0.f;
    for (int i = threadIdx.x; i < A_ * M_; i += 256)
        s += g_partial[(size_t)b * (A_ * M_) + i];
    sh[threadIdx.x] = s;
    __syncthreads();
    for (int st = 128; st > 0; st >>= 1) {
        if (threadIdx.x < st) sh[threadIdx.x] += sh[threadIdx.x + st];
        __syncthreads();
    }
    if (threadIdx.x == 0)
        out[(species_first ? B_ * A_ : 0) + b] = sh[0] / (float)M_;
}

__global__ void species_kernel(const int* __restrict__ sp, float* __restrict__ out) {
    int i = blockIdx.x * 256 + threadIdx.x;
    if (i < B_ * A_) out[i] = (float)sp[i];
}

extern "C" void kernel_launch(void* const* d_in, const int* in_sizes, int n_in,
                              void* d_out, int out_size) {
    const int*   species = (const int*)  d_in[0];
    const float* aev     = (const float*)d_in[1];
    const float* w0      = (const float*)d_in[2];
    const float* b0      = (const float*)d_in[3];
    const float* w2      = (const float*)d_in[4];
    const float* b2      = (const float*)d_in[5];
    const float* w4      = (const float*)d_in[6];
    const float* b4      = (const float*)d_in[7];
    const float* w6      = (const float*)d_in[8];
    const float* b6      = (const float*)d_in[9];
    float* out = (float*)d_out;

    cudaFuncSetAttribute(nn_hmma, cudaFuncAttributeMaxDynamicSharedMemorySize, SMEM_BYTES);

    nn_hmma<<<A_ * M_, NTHREADS, SMEM_BYTES>>>(aev, w0, b0, w2, b2, w4, b4, w6, b6);

    const int species_first = (out_size >= B_ * A_ + B_) ? 1 : 0;
    if (species_first)
        species_kernel<<<(B_ * A_) / 256, 256>>>(species, out);
    reduce_kernel<<<B_, 256>>>(out, species_first);
}

// round 9
// speedup vs baseline: 2.0758x; 1.1139x over previous
#include <cuda_runtime.h>
#include <cuda_fp16.h>
#include <stdint.h>
#include <math.h>

#define B_   64
#define A_   128
#define M_   8
#define D_   384
#define O0_  256
#define O2_  192
#define O4_  160

// smem pitches (bytes) for X buffers [b][k] fp16: K*2+16 -> conflict-free LDSM rows
#define P0 784     // K=384
#define P1 528     // K=256
#define P2 400     // K=192

#define X0_OFF 0
#define X1_OFF 50176                  // 64*784
#define YF_OFF 83968                  // 50176 + 64*528
#define SMEM_BYTES 127488             // YF_OFF + 160*68*4
#define PF 68      // final f32 Y pitch (floats), layout [o][b]

#define NTHREADS 512

__device__ float g_partial[B_ * A_ * M_];

__device__ __forceinline__ float celu01(float x) {
    return x > 0.f ? x : 0.1f * expm1f(10.f * x);
}

__device__ __forceinline__ uint32_t smem_u32(const void* p) {
    uint32_t a;
    asm("{ .reg .u64 t; cvta.to.shared.u64 t, %1; cvt.u32.u64 %0, t; }" : "=r"(a) : "l"(p));
    return a;
}

// byte offset of logical element k within a permuted X row:
// within each 16-col group, pair p -> phys pair (p>>1)+(p&1)*4, so B-frag lane t
// carries logical k (4t,4t+1)/(4t+2,4t+3), matching contiguous float4 W loads.
__device__ __forceinline__ uint32_t permb(int k) {
    int p  = (k >> 1) & 7;
    int pp = (p >> 1) + ((p & 1) << 2);
    return (uint32_t)(((k & ~15) << 1) + (pp << 2) + ((k & 1) << 1));
}

// pack two floats to fp16x2 (lo half = x, hi half = y)
__device__ __forceinline__ uint32_t cvt2h(float x, float y) {
    uint32_t r;
    asm("cvt.rn.f16x2.f32 %0, %1, %2;" : "=r"(r) : "f"(y), "f"(x));
    return r;
}
// W split: fp16 hi + fp16 residual lo (eff ~22 mantissa bits)
__device__ __forceinline__ void split2h(float x, float y, uint32_t& hi, uint32_t& lo) {
    hi = cvt2h(x, y);
    __half2 h = *reinterpret_cast<__half2*>(&hi);
    lo = cvt2h(x - __low2float(h), y - __high2float(h));
}

__device__ __forceinline__ void ldsm_x4(uint32_t& r0, uint32_t& r1, uint32_t& r2, uint32_t& r3,
                                        uint32_t addr) {
    asm volatile("ldmatrix.sync.aligned.m8n8.x4.shared.b16 {%0,%1,%2,%3}, [%4];"
                 : "=r"(r0), "=r"(r1), "=r"(r2), "=r"(r3) : "r"(addr));
}

__device__ __forceinline__ void mma16816(float c[4], const uint32_t a[4], const uint32_t b[2]) {
    asm volatile(
        "mma.sync.aligned.m16n8k16.row.col.f32.f16.f16.f32 "
        "{%0,%1,%2,%3}, {%4,%5,%6,%7}, {%8,%9}, {%0,%1,%2,%3};"
        : "+f"(c[0]), "+f"(c[1]), "+f"(c[2]), "+f"(c[3])
        : "r"(a[0]), "r"(a[1]), "r"(a[2]), "r"(a[3]), "r"(b[0]), "r"(b[1]));
}

// One layer: D[o][b] = celu(W[o][k] X[k][b] + bias).
// 16 warps, warp w owns m-tile w (w < O/16); each warp computes ALL 8 n-tiles.
// W fp32 streamed (contiguous LDG.128, distance-2 prefetch), split to fp16 hi/lo
// in regs. X single fp16 (permuted); one ldsm.x4 covers TWO n-tiles. 2 MMAs per
// n-tile-kc (Wh*X + Wl*X).
template<int K, int O, int PIN, int POUT, bool FINAL>
__device__ __forceinline__ void layer(
    const float* __restrict__ Wg, const float* __restrict__ bias,
    const char* __restrict__ Xin, char* __restrict__ Yout, float* __restrict__ Yf)
{
    const int lane  = threadIdx.x & 31;
    const int warp  = threadIdx.x >> 5;
    const int group = lane >> 2;
    const int tig   = lane & 3;
    constexpr int NMT = O / 16;
    constexpr int NK  = K / 16;
    if (warp >= NMT) return;

    // ldmatrix addresses: pair jj covers n-tiles 2jj, 2jj+1.
    // quad q: q>>1 selects sub-tile, q&1 selects k-half (16B offset).
    const int q = lane >> 3;
    const int rr = lane & 7;
    const uint32_t xbase = smem_u32(Xin);
    uint32_t aj[4];
#pragma unroll
    for (int jj = 0; jj < 4; jj++)
        aj[jj] = xbase + (uint32_t)((jj * 16 + (q >> 1) * 8 + rr) * PIN + (q & 1) * 16);

    float acc[8][4];
#pragma unroll
    for (int j = 0; j < 8; j++)
#pragma unroll
        for (int e = 0; e < 4; e++) acc[j][e] = 0.f;

    const float* wp0 = Wg + (size_t)(warp * 16 + group) * K + tig * 4;
    const float* wp1 = wp0 + 8 * K;

    // parity double-buffers, prefetch distance 2
    float4 e0, e1, o0v, o1v;
    e0  = *(const float4*)(wp0);
    e1  = *(const float4*)(wp1);
    o0v = *(const float4*)(wp0 + 16);
    o1v = *(const float4*)(wp1 + 16);

#pragma unroll 2
    for (int kc = 0; kc < NK; kc++) {
        const bool even = (kc & 1) == 0;
        float4 r0 = even ? e0 : o0v;
        float4 r1 = even ? e1 : o1v;

        // B fragments: 8 n-tiles via 4 ldsm.x4 (two n-tiles per instruction)
        uint32_t bb[4][4];
#pragma unroll
        for (int jj = 0; jj < 4; jj++)
            ldsm_x4(bb[jj][0], bb[jj][1], bb[jj][2], bb[jj][3],
                    aj[jj] + (uint32_t)(kc * 32));

        // split W chunk to fp16 hi/lo fragments
        uint32_t ah[4], al[4];
        split2h(r0.x, r0.y, ah[0], al[0]);
        split2h(r1.x, r1.y, ah[1], al[1]);
        split2h(r0.z, r0.w, ah[2], al[2]);
        split2h(r1.z, r1.w, ah[3], al[3]);

        // prefetch kc+2 into the parity buffer just consumed
        if (kc + 2 < NK) {
            const float* p0 = wp0 + (kc + 2) * 16;
            const float* p1 = wp1 + (kc + 2) * 16;
            if (even) { e0 = *(const float4*)p0;  e1 = *(const float4*)p1; }
            else      { o0v = *(const float4*)p0; o1v = *(const float4*)p1; }
        }

#pragma unroll
        for (int jj = 0; jj < 4; jj++) {
            mma16816(acc[2 * jj],     ah, &bb[jj][0]);
            mma16816(acc[2 * jj],     al, &bb[jj][0]);
            mma16816(acc[2 * jj + 1], ah, &bb[jj][2]);
            mma16816(acc[2 * jj + 1], al, &bb[jj][2]);
        }
    }

    // epilogue
    const int o0 = warp * 16 + group;
    const int o1 = o0 + 8;
    const float bv0 = __ldg(bias + o0);
    const float bv1 = __ldg(bias + o1);
    const uint32_t po0 = permb(o0);
    const uint32_t po1 = permb(o1);
#pragma unroll
    for (int j = 0; j < 8; j++) {
        const int bc = j * 8 + tig * 2;
        float v00 = celu01(acc[j][0] + bv0);
        float v01 = celu01(acc[j][1] + bv0);
        float v10 = celu01(acc[j][2] + bv1);
        float v11 = celu01(acc[j][3] + bv1);
        if (!FINAL) {
            *(__half*)(Yout + (size_t)bc * POUT + po0)       = __float2half_rn(v00);
            *(__half*)(Yout + (size_t)(bc + 1) * POUT + po0) = __float2half_rn(v01);
            *(__half*)(Yout + (size_t)bc * POUT + po1)       = __float2half_rn(v10);
            *(__half*)(Yout + (size_t)(bc + 1) * POUT + po1) = __float2half_rn(v11);
        } else {
            Yf[o0 * PF + bc]     = v00;
            Yf[o0 * PF + bc + 1] = v01;
            Yf[o1 * PF + bc]     = v10;
            Yf[o1 * PF + bc + 1] = v11;
        }
    }
}

__global__ void __launch_bounds__(NTHREADS, 1)
nn_hmma(const float* __restrict__ aev,
        const float* __restrict__ w0, const float* __restrict__ b0,
        const float* __restrict__ w2, const float* __restrict__ b2,
        const float* __restrict__ w4, const float* __restrict__ b4,
        const float* __restrict__ w6, const float* __restrict__ b6)
{
    extern __shared__ char sm[];
    const int tid = threadIdx.x;
    const int am = blockIdx.x, a = am >> 3;

    // init X0 from aev: [b][k] fp16, k-permuted within 16-groups
#pragma unroll
    for (int it = 0; it < 24; it++) {
        int f = (it * NTHREADS + tid) * 2;
        int b = f / D_;
        int k = f % D_;
        float2 v = *(const float2*)(aev + ((size_t)b * A_ + a) * D_ + k);
        *(uint32_t*)(sm + X0_OFF + (size_t)b * P0 + permb(k)) = cvt2h(v.x, v.y);
    }
    __syncthreads();

    layer<D_, O0_, P0, P1, false>(
        w0 + (size_t)am * O0_ * D_, b0 + (size_t)am * O0_,
        sm + X0_OFF, sm + X1_OFF, nullptr);
    __syncthreads();

    layer<O0_, O2_, P1, P2, false>(
        w2 + (size_t)am * O2_ * O0_, b2 + (size_t)am * O2_,
        sm + X1_OFF, sm + X0_OFF, nullptr);
    __syncthreads();

    layer<O2_, O4_, P2, 0, true>(
        w4 + (size_t)am * O4_ * O2_, b4 + (size_t)am * O4_,
        sm + X0_OFF, nullptr, (float*)(sm + YF_OFF));
    __syncthreads();

    // final dot: energy contribution per (b, am). 512 threads: 8 per b.
    const float* Yf = (const float*)(sm + YF_OFF);
    const float* w6p = w6 + (size_t)am * O4_;
    const int b = tid >> 3;
    const int part = tid & 7;
    float acc = 0.f;
#pragma unroll
    for (int i = 0; i < 20; i++) {
        int k = part * 20 + i;
        acc += __ldg(w6p + k) * Yf[k * PF + b];
    }
    acc += __shfl_xor_sync(0xffffffffu, acc, 1);
    acc += __shfl_xor_sync(0xffffffffu, acc, 2);
    acc += __shfl_xor_sync(0xffffffffu, acc, 4);
    if (part == 0)
        g_partial[(size_t)b * (A_ * M_) + am] = acc + __ldg(b6 + am);
}

// ---------------- output assembly ----------------
__global__ void reduce_kernel(float* __restrict__ out, int species_first) {
    __shared__ float sh[256];
    const int b = blockIdx.x;
    float s = 0.f;
    for (int i = threadIdx.x; i < A_ * M_; i += 256)
        s += g_partial[(size_t)b * (A_ * M_) + i];
    sh[threadIdx.x] = s;
    __syncthreads();
    for (int st = 128; st > 0; st >>= 1) {
        if (threadIdx.x < st) sh[threadIdx.x] += sh[threadIdx.x + st];
        __syncthreads();
    }
    if (threadIdx.x == 0)
        out[(species_first ? B_ * A_ : 0) + b] = sh[0] / (float)M_;
}

__global__ void species_kernel(const int* __restrict__ sp, float* __restrict__ out) {
    int i = blockIdx.x * 256 + threadIdx.x;
    if (i < B_ * A_) out[i] = (float)sp[i];
}

extern "C" void kernel_launch(void* const* d_in, const int* in_sizes, int n_in,
                              void* d_out, int out_size) {
    const int*   species = (const int*)  d_in[0];
    const float* aev     = (const float*)d_in[1];
    const float* w0      = (const float*)d_in[2];
    const float* b0      = (const float*)d_in[3];
    const float* w2      = (const float*)d_in[4];
    const float* b2      = (const float*)d_in[5];
    const float* w4      = (const float*)d_in[6];
    const float* b4      = (const float*)d_in[7];
    const float* w6      = (const float*)d_in[8];
    const float* b6      = (const float*)d_in[9];
    float* out = (float*)d_out;

    cudaFuncSetAttribute(nn_hmma, cudaFuncAttributeMaxDynamicSharedMemorySize, SMEM_BYTES);

    nn_hmma<<<A_ * M_, NTHREADS, SMEM_BYTES>>>(aev, w0, b0, w2, b2, w4, b4, w6, b6);

    const int species_first = (out_size >= B_ * A_ + B_) ? 1 : 0;
    if (species_first)
        species_kernel<<<(B_ * A_) / 256, 256>>>(species, out);
    reduce_kernel<<<B_, 256>>>(out, species_first);
}